// round 6
// baseline (speedup 1.0000x reference)
#include <cuda_runtime.h>
#include <cstdint>
#include <cstddef>

#define H_    300000
#define CIN   16
#define COUT  32
#define KK    27
#define HB    128                     // h per block
#define TB    128                     // threads per block
#define NBLK  ((H_ + HB - 1) / HB)    // 2344
#define NIDX  (H_ * KK)               // 8,100,000
#define COLP  132                     // col row pitch (floats)
#define COLSZ 2120                    // floats per col buffer (max addr 2116, pad)
#define WSZ   (KK * CIN * COUT)       // 13824 weight floats

// Scratch (static device globals: allocation-free per harness rules)
__device__ float4 g_xT4[(size_t)H_ * 4];     // 19.2 MB: x transposed to [h][i]
__device__ float  g_wpk[WSZ];                // staging for repacked weights
__device__ float  g_partials[64 * NBLK];     // rows 0..31 sum(y), 32..63 sum(y^2)
__device__ float  g_scale[COUT];
__device__ float  g_bias[COUT];
__device__ int    g_is64;

// Weights in constant memory: served by the constant port, NOT L1tex.
// layout: c_w4[(k*16+i)*8 + o/4]
__constant__ float4 c_w4[WSZ / 4];           // 55296 B <= 64KB

// packed f32x2 helpers (sm_103a FFMA2 — only reachable via PTX)
__device__ __forceinline__ unsigned long long fma_f32x2(unsigned long long a,
                                                        unsigned long long b,
                                                        unsigned long long c) {
    unsigned long long d;
    asm("fma.rn.f32x2 %0, %1, %2, %3;" : "=l"(d) : "l"(a), "l"(b), "l"(c));
    return d;
}
__device__ __forceinline__ unsigned long long pack_dup(float v) {
    unsigned long long d;
    unsigned int u = __float_as_uint(v);
    asm("mov.b64 %0, {%1, %2};" : "=l"(d) : "r"(u), "r"(u));
    return d;
}
__device__ __forceinline__ void unpack2(unsigned long long p, float& lo, float& hi) {
    unsigned int a, b;
    asm("mov.b64 {%0, %1}, %2;" : "=r"(a), "=r"(b) : "l"(p));
    lo = __uint_as_float(a);
    hi = __uint_as_float(b);
}
__device__ __forceinline__ unsigned long long pack2(float lo, float hi) {
    unsigned long long d;
    asm("mov.b64 %0, {%1, %2};" : "=l"(d) : "r"(__float_as_uint(lo)), "r"(__float_as_uint(hi)));
    return d;
}

// col addressing: row i at i*COLP + ((i>>3)&1)*8  (swizzle keeps STS conflict-free
// across the 4 quads while preserving 16B alignment for LDS.128)
__device__ __forceinline__ int col_row_off(int i) {
    return i * COLP + ((i >> 3) & 1) * 8;
}

// ---------------------------------------------------------------------------
// Kernel 0: detect int64 vs int32 neigh (JAX x64 off => i32). Sample odd words.
// ---------------------------------------------------------------------------
__global__ void detect_kernel(const unsigned int* __restrict__ nv) {
    __shared__ int ok;
    if (threadIdx.x == 0) ok = 1;
    __syncthreads();
    unsigned int v = nv[threadIdx.x * 2000 + 1];   // max idx < 2.05M < 8.1M words
    if (v != 0u && v != 0xFFFFFFFFu) ok = 0;       // benign race: only writes 0
    __syncthreads();
    if (threadIdx.x == 0) g_is64 = ok;
}

// ---------------------------------------------------------------------------
// Kernel 1: repack weights w[o][i][k] -> g_wpk[(k*16+i)*32+o] (o-contiguous).
// (then D2D-memcpy'd into constant memory by the host launcher)
// ---------------------------------------------------------------------------
__global__ void repack_w_kernel(const float* __restrict__ w) {
    int t = blockIdx.x * blockDim.x + threadIdx.x;
    if (t < WSZ) {
        int o = t / (CIN * KK);
        int r = t % (CIN * KK);
        int i = r / KK;
        int k = r % KK;
        g_wpk[(k * CIN + i) * COUT + o] = w[t];
    }
}

// ---------------------------------------------------------------------------
// Kernel 2: transpose x[i][h] -> xT[h][i]; each gather row becomes one 64B line.
// ---------------------------------------------------------------------------
__global__ void transpose_x_kernel(const float* __restrict__ x) {
    int h = blockIdx.x * blockDim.x + threadIdx.x;
    if (h < H_) {
        float v[CIN];
#pragma unroll
        for (int i = 0; i < CIN; i++) v[i] = x[(size_t)i * H_ + h];
#pragma unroll
        for (int j = 0; j < 4; j++)
            g_xT4[(size_t)h * 4 + j] =
                make_float4(v[4 * j], v[4 * j + 1], v[4 * j + 2], v[4 * j + 3]);
    }
}

// ---------------------------------------------------------------------------
// Kernel 3: register-blocked GEMM y[32,128] = W[32,432] * col[432,128] per
// block. Double-buffered cooperative gather; FFMA2; weights via constant port;
// indices staged once per block in smem; conflict-free STS via swizzle.
// 4 warps: warp = o-group. Thread tile 8o x 4h.
// ---------------------------------------------------------------------------
__global__ void __launch_bounds__(TB, 6) conv_kernel(const int* __restrict__ neigh32,
                                                     float* __restrict__ out) {
    __shared__ float col[2 * COLSZ];   // 16960 B
    __shared__ int   sidx[HB * KK];    // 13824 B

    const int tid  = threadIdx.x;
    const int lane = tid & 31;
    const int wid  = tid >> 5;        // 0..3 = o-group
    const int h0   = blockIdx.x * HB;
    const int og   = wid * 8;         // warp's 8 output channels
    const int hg   = lane * 4;        // thread's 4 h (contiguous)

    // Stage this block's 128*27 indices once (coalesced; i64 low-word read).
    {
        const int is64 = g_is64;
        const int base = h0 * KK;
#pragma unroll 1
        for (int t = tid; t < HB * KK; t += TB) {
            int gi = base + t;
            int v = -1;
            if (gi < NIDX) v = neigh32[is64 ? 2 * gi : gi];
            sidx[t] = v;
        }
    }
    __syncthreads();

    const int q     = tid & 3;        // which float4 of a gathered row
    const int rbase = tid >> 2;       // 0..31; rows r = rbase + 32j
    const int sbase = 4 * q * COLP + (q >> 1) * 8;   // swizzled store base

    // Cooperative gather of col tile for step k: 4 lanes fetch one 64B row.
    auto gather = [&](int k, float* dst) {
#pragma unroll
        for (int j = 0; j < 4; j++) {
            int r   = rbase + 32 * j;
            int idx = sidx[r * KK + k];
            float4 v = make_float4(0.f, 0.f, 0.f, 0.f);
            if (idx >= 0 && idx < H_) v = g_xT4[(size_t)idx * 4 + q];
            float* p = dst + sbase + r;
            p[0 * COLP] = v.x;
            p[1 * COLP] = v.y;
            p[2 * COLP] = v.z;
            p[3 * COLP] = v.w;
        }
    };

    gather(0, col);
    __syncthreads();

    unsigned long long acc[4][4];   // [o-pair][h]
#pragma unroll
    for (int a = 0; a < 4; a++)
#pragma unroll
        for (int b = 0; b < 4; b++) acc[a][b] = 0ull;

#pragma unroll 1
    for (int k = 0; k < KK; k++) {
        const float* cc = col + (k & 1) * COLSZ;
        float*       cn = col + ((k + 1) & 1) * COLSZ;
        if (k + 1 < KK) gather(k + 1, cn);

#pragma unroll
        for (int i = 0; i < CIN; i++) {
            float4 c4 = *reinterpret_cast<const float4*>(cc + col_row_off(i) + hg);
            unsigned long long cd[4] = {pack_dup(c4.x), pack_dup(c4.y),
                                        pack_dup(c4.z), pack_dup(c4.w)};
            // 8 weights for this warp: two LDC.128 from the constant port
            float4 wa = c_w4[(k * CIN + i) * 8 + wid * 2];
            float4 wb = c_w4[(k * CIN + i) * 8 + wid * 2 + 1];
            unsigned long long w01 = pack2(wa.x, wa.y), w23 = pack2(wa.z, wa.w);
            unsigned long long w45 = pack2(wb.x, wb.y), w67 = pack2(wb.z, wb.w);
#pragma unroll
            for (int hh = 0; hh < 4; hh++) {
                acc[0][hh] = fma_f32x2(w01, cd[hh], acc[0][hh]);
                acc[1][hh] = fma_f32x2(w23, cd[hh], acc[1][hh]);
                acc[2][hh] = fma_f32x2(w45, cd[hh], acc[2][hh]);
                acc[3][hh] = fma_f32x2(w67, cd[hh], acc[3][hh]);
            }
        }
        __syncthreads();
    }

    // Unpack, write y (coalesced float4 per o), per-warp BN partials.
    const bool valid = (h0 + hg) < H_;   // quad-granular: H_ % 4 == 0
    float s[8], ss[8];
#pragma unroll
    for (int op = 0; op < 4; op++) {
        float lo[4], hi[4];
#pragma unroll
        for (int hh = 0; hh < 4; hh++) unpack2(acc[op][hh], lo[hh], hi[hh]);
        if (valid) {
            *reinterpret_cast<float4*>(out + (size_t)(og + 2 * op) * H_ + h0 + hg) =
                make_float4(lo[0], lo[1], lo[2], lo[3]);
            *reinterpret_cast<float4*>(out + (size_t)(og + 2 * op + 1) * H_ + h0 + hg) =
                make_float4(hi[0], hi[1], hi[2], hi[3]);
        }
        s[2 * op]      = lo[0] + lo[1] + lo[2] + lo[3];
        s[2 * op + 1]  = hi[0] + hi[1] + hi[2] + hi[3];
        ss[2 * op]     = lo[0] * lo[0] + lo[1] * lo[1] + lo[2] * lo[2] + lo[3] * lo[3];
        ss[2 * op + 1] = hi[0] * hi[0] + hi[1] * hi[1] + hi[2] * hi[2] + hi[3] * hi[3];
    }
#pragma unroll
    for (int oo = 0; oo < 8; oo++) {
        float v = s[oo], qv = ss[oo];
#pragma unroll
        for (int sft = 16; sft > 0; sft >>= 1) {
            v  += __shfl_down_sync(0xffffffffu, v, sft);
            qv += __shfl_down_sync(0xffffffffu, qv, sft);
        }
        if (lane == 0) {
            g_partials[(og + oo) * NBLK + blockIdx.x]      = v;
            g_partials[(32 + og + oo) * NBLK + blockIdx.x] = qv;
        }
    }
}

// ---------------------------------------------------------------------------
// Kernel 4: one block per channel; deterministic fp64 reduction -> scale/bias.
// ---------------------------------------------------------------------------
__global__ void stats_kernel(const float* __restrict__ gamma,
                             const float* __restrict__ beta) {
    const int o = blockIdx.x;
    double s1 = 0.0, s2 = 0.0;
    for (int b = threadIdx.x; b < NBLK; b += blockDim.x) {
        s1 += (double)g_partials[o * NBLK + b];
        s2 += (double)g_partials[(32 + o) * NBLK + b];
    }
    __shared__ double r1[256], r2[256];
    r1[threadIdx.x] = s1;
    r2[threadIdx.x] = s2;
    __syncthreads();
    for (int sft = 128; sft > 0; sft >>= 1) {
        if (threadIdx.x < sft) {
            r1[threadIdx.x] += r1[threadIdx.x + sft];
            r2[threadIdx.x] += r2[threadIdx.x + sft];
        }
        __syncthreads();
    }
    if (threadIdx.x == 0) {
        double mean = r1[0] / (double)H_;
        double var  = r2[0] / (double)H_ - mean * mean;
        float rstd  = rsqrtf((float)(var + 1e-5));
        float sc    = rstd * gamma[o];
        g_scale[o]  = sc;
        g_bias[o]   = beta[o] - (float)mean * sc;
    }
}

// ---------------------------------------------------------------------------
// Kernel 5: normalize in place (float4; H % 4 == 0).
// ---------------------------------------------------------------------------
__global__ void bn_kernel(float* __restrict__ out) {
    const int o = blockIdx.y;
    const int t = blockIdx.x * blockDim.x + threadIdx.x;
    const float sc = g_scale[o], bi = g_bias[o];
    float4* p = reinterpret_cast<float4*>(out + (size_t)o * H_);
    if (t < H_ / 4) {
        float4 v = p[t];
        v.x = v.x * sc + bi;
        v.y = v.y * sc + bi;
        v.z = v.z * sc + bi;
        v.w = v.w * sc + bi;
        p[t] = v;
    }
}

// ---------------------------------------------------------------------------
extern "C" void kernel_launch(void* const* d_in, const int* in_sizes, int n_in,
                              void* d_out, int out_size) {
    const float* x     = (const float*)d_in[0];  // (1,16,300000,1)
    const float* w     = (const float*)d_in[1];  // (32,16,27)
    const float* gamma = (const float*)d_in[2];  // (32,)
    const float* beta  = (const float*)d_in[3];  // (32,)
    const void*  neigh = d_in[4];                // (300000,27) i64 or i32
    float*       out   = (float*)d_out;          // (1,32,300000,1)

    detect_kernel<<<1, 1024>>>((const unsigned int*)neigh);
    repack_w_kernel<<<(WSZ + 255) / 256, 256>>>(w);

    // Push repacked weights into constant memory (D2D memcpy node — graph-legal)
    void* wpk_ptr = nullptr;
    cudaGetSymbolAddress(&wpk_ptr, g_wpk);
    cudaMemcpyToSymbolAsync(c_w4, wpk_ptr, WSZ * sizeof(float), 0,
                            cudaMemcpyDeviceToDevice, 0);

    transpose_x_kernel<<<(H_ + 255) / 256, 256>>>(x);
    conv_kernel<<<NBLK, TB>>>((const int*)neigh, out);
    stats_kernel<<<COUT, 256>>>(gamma, beta);
    bn_kernel<<<dim3((H_ / 4 + 255) / 256, COUT), 256>>>(out);
}